// round 2
// baseline (speedup 1.0000x reference)
#include <cuda_runtime.h>
#include <math.h>

#define HW 65536            // 256*256
#define NPIX 256

// ---------------- scratch (device globals) -----------------------------------
__device__ float  g_pooled[2*192*1024];
__device__ float4 g_params[2*6*1024];          // {sx, sy, px, py} per (b,head,wy,wx)
__device__ float  g_rpb  [6*4096];             // precomputed rpb[h][q][k]
__device__ float  g_q    [2*192*HW];
__device__ float  g_qpan [2*192*HW];
__device__ float  g_k    [2*192*HW];
__device__ float  g_v    [2*192*HW];
__device__ float  g_attn [2*192*HW];
__device__ float  g_attnp[2*192*HW];

// ---------------- f32x2 helpers ----------------------------------------------
typedef unsigned long long u64t;
#define FMA2(d,a,b) asm volatile("fma.rn.f32x2 %0, %1, %2, %0;" : "+l"(d) : "l"(a), "l"(b))
#define ADD2(d,a,b) asm volatile("add.rn.f32x2 %0, %1, %2;" : "=l"(d) : "l"(a), "l"(b))
__device__ __forceinline__ u64t pack2(float lo, float hi) {
    u64t r; asm("mov.b64 %0, {%1,%2};" : "=l"(r) : "f"(lo), "f"(hi)); return r;
}
__device__ __forceinline__ float2 unpack2(u64t p) {
    float2 r; asm("mov.b64 {%0,%1}, %2;" : "=f"(r.x), "=f"(r.y) : "l"(p)); return r;
}

// ---------------- 1) 8x8 window mean + leaky ----------------------------------
__global__ void __launch_bounds__(256) pool_kernel(const float* __restrict__ x) {
    int idx = blockIdx.x * 256 + threadIdx.x;
    if (idx >= 2*192*1024) return;
    int wx = idx & 31, wy = (idx >> 5) & 31;
    int c  = (idx >> 10) % 192, b = idx / (192*1024);
    const float* p = x + ((b*192 + c)*256 + wy*8)*256 + wx*8;
    float s = 0.f;
    #pragma unroll
    for (int i = 0; i < 8; i++) {
        #pragma unroll
        for (int j = 0; j < 8; j++) s += p[i*256 + j];
    }
    s *= (1.0f/64.0f);
    g_pooled[idx] = (s >= 0.f) ? s : 0.01f*s;
}

// ---------------- 2) per-window offset/scale params ----------------------------
__global__ void params_kernel(const float* __restrict__ off_w, const float* __restrict__ off_b,
                              const float* __restrict__ sc_w,  const float* __restrict__ sc_b) {
    int idx = blockIdx.x * blockDim.x + threadIdx.x;
    if (idx >= 2*6*1024) return;
    int wx = idx & 31, wy = (idx >> 5) & 31;
    int h  = (idx >> 10) % 6, b = idx / (6*1024);
    const float* pv = g_pooled + b*192*1024 + wy*32 + wx;
    float ox = off_b[h*2], oy = off_b[h*2+1];
    float sx = sc_b[h*2],  sy = sc_b[h*2+1];
    const float* owx = off_w + (h*2)*192; const float* owy = owx + 192;
    const float* swx = sc_w  + (h*2)*192; const float* swy = swx + 192;
    for (int c = 0; c < 192; c++) {
        float p = pv[c*1024];
        ox += owx[c]*p; oy += owy[c]*p;
        sx += swx[c]*p; sy += swy[c]*p;
    }
    float4 r; r.x = sx; r.y = sy; r.z = ox*(127.5f/32.0f); r.w = oy*(127.5f/32.0f);
    g_params[idx] = r;
}

// ---------------- 2b) rpb table expansion -------------------------------------
__global__ void rpb_kernel(const float* __restrict__ rpb_table) {
    int idx = blockIdx.x * blockDim.x + threadIdx.x;
    if (idx >= 6*4096) return;
    int h = idx / 4096, r = idx & 4095;
    int q = r >> 6, k2 = r & 63;
    int rpi = ((q >> 3) - (k2 >> 3) + 7)*15 + ((q & 7) - (k2 & 7) + 7);
    g_rpb[idx] = rpb_table[rpi*6 + h];
}

// ---------------- 3) qkv GEMM (f32x2): C[M,65536] = W[M,192]*X[192,65536] -----
// block tile 64m x 128n, 256 threads, thread tile 4m x 8n
// mode 0: M=576 -> route {g_qpan,g_k,g_v}. mode 1: M=192 -> g_q.
__global__ void __launch_bounds__(256) qkv_gemm(const float* __restrict__ X,
                                                const float* __restrict__ W,
                                                const float* __restrict__ bias, int mode) {
    __shared__ float As2[16][128];   // duplicated A: [k][2m],[k][2m+1]
    __shared__ float Bs [16][128];
    int n0 = blockIdx.x * 128, m0 = blockIdx.y * 64, b = blockIdx.z;
    const float* Xb = X + b*192*HW;
    int tid = threadIdx.x;
    int tx = tid & 15, ty = tid >> 4;
    int lam = tid >> 2, lak = (tid & 3) * 4;
    u64t acc[16];
    #pragma unroll
    for (int i = 0; i < 16; i++) acc[i] = 0ULL;
    for (int kk = 0; kk < 192; kk += 16) {
        float4 wa = *(const float4*)(W + (m0 + lam)*192 + kk + lak);
        *(float2*)&As2[lak+0][2*lam] = make_float2(wa.x, wa.x);
        *(float2*)&As2[lak+1][2*lam] = make_float2(wa.y, wa.y);
        *(float2*)&As2[lak+2][2*lam] = make_float2(wa.z, wa.z);
        *(float2*)&As2[lak+3][2*lam] = make_float2(wa.w, wa.w);
        #pragma unroll
        for (int i = 0; i < 2; i++) {
            int idx = tid + i*256;
            int k = idx >> 5, n4 = (idx & 31) * 4;
            *(float4*)&Bs[k][n4] = *(const float4*)(Xb + (kk + k)*HW + n0 + n4);
        }
        __syncthreads();
        #pragma unroll
        for (int k = 0; k < 16; k++) {
            ulonglong2 av0 = *(const ulonglong2*)&As2[k][ty*8];
            ulonglong2 av1 = *(const ulonglong2*)&As2[k][ty*8 + 4];
            ulonglong2 bv0 = *(const ulonglong2*)&Bs[k][tx*8];
            ulonglong2 bv1 = *(const ulonglong2*)&Bs[k][tx*8 + 4];
            u64t a2[4] = {av0.x, av0.y, av1.x, av1.y};
            u64t b2[4] = {bv0.x, bv0.y, bv1.x, bv1.y};
            #pragma unroll
            for (int u = 0; u < 4; u++)
                #pragma unroll
                for (int p = 0; p < 4; p++) FMA2(acc[u*4+p], a2[u], b2[p]);
        }
        __syncthreads();
    }
    #pragma unroll
    for (int u = 0; u < 4; u++) {
        int m = m0 + ty*4 + u;
        float bi = bias[m];
        int which = m / 192, c = m - which*192;
        float* dst;
        if (mode == 1) dst = g_q;
        else dst = (which == 0) ? g_qpan : ((which == 1) ? g_k : g_v);
        float o[8];
        #pragma unroll
        for (int p = 0; p < 4; p++) {
            float2 t = unpack2(acc[u*4+p]);
            o[2*p] = t.x + bi; o[2*p+1] = t.y + bi;
        }
        float* base = dst + (b*192 + c)*HW + n0 + tx*8;
        *(float4*)(base)     = make_float4(o[0], o[1], o[2], o[3]);
        *(float4*)(base + 4) = make_float4(o[4], o[5], o[6], o[7]);
    }
}

// ---------------- 4) fused grid-sample + window attention (f32x2) -------------
// block = one (b, wy, wx, head); threads 0-63: q stream, 64-127: q_pan stream.
#define KVP 36   // padded row (16B-aligned, mild bank-conflict on gather STS)
__global__ void __launch_bounds__(128) attn_kernel() {
    __shared__ float ksm[64][KVP];
    __shared__ float vsm[64][KVP];
    __shared__ float rpbsm[4096];
    __shared__ float gxs[64], gys[64];
    int bx = blockIdx.x;
    int h = bx % 6; int t = bx / 6;
    int wx = t & 31, wy = (t >> 5) & 31, b = t >> 10;
    int tid = threadIdx.x;

    if (tid < 64) {
        int i = tid >> 3, j = tid & 7;
        float4 p = g_params[((b*6 + h)*32 + wy)*32 + wx];
        gxs[tid] = (float)(wx*8 + j) + ((float)j - 3.5f)*p.x + p.z;
        gys[tid] = (float)(wy*8 + i) + ((float)i - 3.5f)*p.y + p.w;
    }
    // rpb: coalesced float4 copy from precomputed table
    {
        const float4* src = (const float4*)(g_rpb + h*4096);
        float4* dst4 = (float4*)rpbsm;
        #pragma unroll
        for (int i = 0; i < 8; i++) dst4[tid + i*128] = src[tid + i*128];
    }
    __syncthreads();

    int cbase = (b*192 + h*32)*HW;
    const float* kb = g_k + cbase;
    const float* vb = g_v + cbase;
    // gather: warp lanes span positions (nearby pixels) for sector locality
    #pragma unroll
    for (int it = 0; it < 16; it++) {
        int idx = tid + it*128;
        int pos = idx & 63, d = idx >> 6;
        float gx = gxs[pos], gy = gys[pos];
        float xf = floorf(gx), yf = floorf(gy);
        int x0 = (int)xf, y0 = (int)yf;
        float fx = gx - xf, fy = gy - yf;
        int off = d*HW;
        float kacc = 0.f, vacc = 0.f;
        bool vx0 = (x0 >= 0) & (x0 < NPIX), vx1 = (x0+1 >= 0) & (x0+1 < NPIX);
        bool vy0 = (y0 >= 0) & (y0 < NPIX), vy1 = (y0+1 >= 0) & (y0+1 < NPIX);
        if (vx0 & vy0) { float w = (1.f-fx)*(1.f-fy); int o = off + y0*256 + x0;       kacc += w*kb[o]; vacc += w*vb[o]; }
        if (vx1 & vy0) { float w = fx*(1.f-fy);       int o = off + y0*256 + x0+1;     kacc += w*kb[o]; vacc += w*vb[o]; }
        if (vx0 & vy1) { float w = (1.f-fx)*fy;       int o = off + (y0+1)*256 + x0;   kacc += w*kb[o]; vacc += w*vb[o]; }
        if (vx1 & vy1) { float w = fx*fy;             int o = off + (y0+1)*256 + x0+1; kacc += w*kb[o]; vacc += w*vb[o]; }
        ksm[pos][d] = kacc;
        vsm[pos][d] = vacc;
    }
    __syncthreads();

    int qi = tid & 63;
    const float* qb = ((tid < 64) ? g_q : g_qpan) + cbase;
    int i = qi >> 3, j = qi & 7;
    int pix = (wy*8 + i)*256 + wx*8 + j;
    u64t q2[16];
    {
        float qf[32];
        #pragma unroll
        for (int d = 0; d < 32; d++) qf[d] = qb[d*HW + pix] * 0.17677669529663687f;
        #pragma unroll
        for (int d = 0; d < 16; d++) q2[d] = pack2(qf[2*d], qf[2*d+1]);
    }

    float sc[64];
    float mx = -1e30f;
    const float* rpbrow = rpbsm + qi*64;
    #pragma unroll
    for (int k = 0; k < 64; k++) {
        const ulonglong2* kr = (const ulonglong2*)&ksm[k][0];
        u64t ap0 = 0ULL, ap1 = 0ULL, ap2 = 0ULL, ap3 = 0ULL;
        #pragma unroll
        for (int g = 0; g < 4; g++) {
            ulonglong2 kv0 = kr[2*g];
            ulonglong2 kv1 = kr[2*g+1];
            FMA2(ap0, q2[4*g+0], kv0.x);
            FMA2(ap1, q2[4*g+1], kv0.y);
            FMA2(ap2, q2[4*g+2], kv1.x);
            FMA2(ap3, q2[4*g+3], kv1.y);
        }
        u64t s01, s23, s03;
        ADD2(s01, ap0, ap1); ADD2(s23, ap2, ap3); ADD2(s03, s01, s23);
        float2 tv = unpack2(s03);
        float s = tv.x + tv.y + rpbrow[k];
        sc[k] = s;
        mx = fmaxf(mx, s);
    }
    float sum = 0.f;
    #pragma unroll
    for (int k = 0; k < 64; k++) { float e = __expf(sc[k] - mx); sc[k] = e; sum += e; }
    float inv = 1.0f/sum;

    u64t ov2[16];
    #pragma unroll
    for (int d = 0; d < 16; d++) ov2[d] = 0ULL;
    #pragma unroll
    for (int k = 0; k < 64; k++) {
        float a = sc[k]*inv;
        u64t a2 = pack2(a, a);
        const ulonglong2* vr = (const ulonglong2*)&vsm[k][0];
        #pragma unroll
        for (int g = 0; g < 8; g++) {
            ulonglong2 vv = vr[g];
            FMA2(ov2[2*g],   a2, vv.x);
            FMA2(ov2[2*g+1], a2, vv.y);
        }
    }
    float* dst = ((tid < 64) ? g_attn : g_attnp) + cbase;
    #pragma unroll
    for (int d = 0; d < 16; d++) {
        float2 tv = unpack2(ov2[d]);
        dst[(2*d)*HW + pix]   = tv.x;
        dst[(2*d+1)*HW + pix] = tv.y;
    }
}

// ---------------- 5) proj GEMM (f32x2) -----------------------------------------
__global__ void __launch_bounds__(256) proj_gemm(const float* __restrict__ W,
                                                 const float* __restrict__ bias,
                                                 float* __restrict__ out) {
    __shared__ float As2[16][128];
    __shared__ float Bs [16][128];
    int z = blockIdx.z; int b = z & 1; int strm = z >> 1;
    const float* Xb = (strm ? g_attnp : g_attn) + b*192*HW;
    float* dstb = out + strm*(2*192*HW) + b*192*HW;
    int n0 = blockIdx.x * 128, m0 = blockIdx.y * 64;
    int tid = threadIdx.x;
    int tx = tid & 15, ty = tid >> 4;
    int lam = tid >> 2, lak = (tid & 3) * 4;
    u64t acc[16];
    #pragma unroll
    for (int i = 0; i < 16; i++) acc[i] = 0ULL;
    for (int kk = 0; kk < 192; kk += 16) {
        float4 wa = *(const float4*)(W + (m0 + lam)*192 + kk + lak);
        *(float2*)&As2[lak+0][2*lam] = make_float2(wa.x, wa.x);
        *(float2*)&As2[lak+1][2*lam] = make_float2(wa.y, wa.y);
        *(float2*)&As2[lak+2][2*lam] = make_float2(wa.z, wa.z);
        *(float2*)&As2[lak+3][2*lam] = make_float2(wa.w, wa.w);
        #pragma unroll
        for (int i = 0; i < 2; i++) {
            int idx = tid + i*256;
            int k = idx >> 5, n4 = (idx & 31) * 4;
            *(float4*)&Bs[k][n4] = *(const float4*)(Xb + (kk + k)*HW + n0 + n4);
        }
        __syncthreads();
        #pragma unroll
        for (int k = 0; k < 16; k++) {
            ulonglong2 av0 = *(const ulonglong2*)&As2[k][ty*8];
            ulonglong2 av1 = *(const ulonglong2*)&As2[k][ty*8 + 4];
            ulonglong2 bv0 = *(const ulonglong2*)&Bs[k][tx*8];
            ulonglong2 bv1 = *(const ulonglong2*)&Bs[k][tx*8 + 4];
            u64t a2[4] = {av0.x, av0.y, av1.x, av1.y};
            u64t b2[4] = {bv0.x, bv0.y, bv1.x, bv1.y};
            #pragma unroll
            for (int u = 0; u < 4; u++)
                #pragma unroll
                for (int p = 0; p < 4; p++) FMA2(acc[u*4+p], a2[u], b2[p]);
        }
        __syncthreads();
    }
    #pragma unroll
    for (int u = 0; u < 4; u++) {
        int m = m0 + ty*4 + u;
        float bi = bias[m];
        float o[8];
        #pragma unroll
        for (int p = 0; p < 4; p++) {
            float2 t = unpack2(acc[u*4+p]);
            o[2*p] = t.x + bi; o[2*p+1] = t.y + bi;
        }
        float* base = dstb + m*HW + n0 + tx*8;
        *(float4*)(base)     = make_float4(o[0], o[1], o[2], o[3]);
        *(float4*)(base + 4) = make_float4(o[4], o[5], o[6], o[7]);
    }
}

// ---------------- launch --------------------------------------------------------
extern "C" void kernel_launch(void* const* d_in, const int* in_sizes, int n_in,
                              void* d_out, int out_size) {
    const float* x      = (const float*)d_in[0];
    const float* lms    = (const float*)d_in[1];
    const float* qkv_w  = (const float*)d_in[2];
    const float* qkv_b  = (const float*)d_in[3];
    const float* off_w  = (const float*)d_in[4];
    const float* off_b  = (const float*)d_in[5];
    const float* sc_w   = (const float*)d_in[6];
    const float* sc_b   = (const float*)d_in[7];
    const float* proj_w = (const float*)d_in[8];
    const float* proj_b = (const float*)d_in[9];
    const float* rpb    = (const float*)d_in[10];
    float* out = (float*)d_out;

    pool_kernel<<<(2*192*1024 + 255)/256, 256>>>(x);
    params_kernel<<<(2*6*1024 + 255)/256, 256>>>(off_w, off_b, sc_w, sc_b);
    rpb_kernel<<<(6*4096 + 255)/256, 256>>>(rpb);
    qkv_gemm<<<dim3(512, 9, 2), 256>>>(x,   qkv_w, qkv_b, 0);
    qkv_gemm<<<dim3(512, 3, 2), 256>>>(lms, qkv_w, qkv_b, 1);
    attn_kernel<<<2*32*32*6, 128>>>();
    proj_gemm<<<dim3(512, 3, 4), 256>>>(proj_w, proj_b, out);
}

// round 4
// speedup vs baseline: 1.4997x; 1.4997x over previous
#include <cuda_runtime.h>
#include <cuda_bf16.h>
#include <mma.h>
#include <math.h>
#include <cstdint>

using namespace nvcuda;

#define HW 65536            // 256*256
#define NPIX 256
#define KTOT 576            // 3-term split-K: [hi | lo | hi] x [Whi | Whi | Wlo]
#define KCH 64

// ---------------- scratch (device globals) -----------------------------------
__device__ float  g_pooled[2*192*1024];
__device__ float4 g_params[2*6*1024];
__device__ float  g_rpb  [6*4096];
// split-bf16 transposed activations: [pixel][576] = [hi(192) | lo(192) | hi(192)]
__device__ __nv_bfloat16 g_xt[(size_t)2*HW*KTOT];
__device__ __nv_bfloat16 g_lt[(size_t)2*HW*KTOT];
__device__ __nv_bfloat16 g_at[(size_t)4*HW*KTOT];   // attn out: (stream*2+b)
// split-bf16 weights: [m][576] = [Whi | Whi | Wlo]
__device__ __nv_bfloat16 g_wq[576*KTOT];
__device__ __nv_bfloat16 g_wp[192*KTOT];
// fp32 feature-major qkv
__device__ float  g_q    [(size_t)2*192*HW];
__device__ float  g_qpan [(size_t)2*192*HW];
__device__ float  g_k    [(size_t)2*192*HW];
__device__ float  g_v    [(size_t)2*192*HW];

// ---------------- 1) 8x8 window mean + leaky ----------------------------------
__global__ void __launch_bounds__(256) pool_kernel(const float* __restrict__ x) {
    int idx = blockIdx.x * 256 + threadIdx.x;
    if (idx >= 2*192*1024) return;
    int wx = idx & 31, wy = (idx >> 5) & 31;
    int c  = (idx >> 10) % 192, b = idx / (192*1024);
    const float* p = x + ((size_t)(b*192 + c)*256 + wy*8)*256 + wx*8;
    float s = 0.f;
    #pragma unroll
    for (int i = 0; i < 8; i++)
        #pragma unroll
        for (int j = 0; j < 8; j++) s += p[i*256 + j];
    s *= (1.0f/64.0f);
    g_pooled[idx] = (s >= 0.f) ? s : 0.01f*s;
}

// ---------------- 2) per-window offset/scale params ----------------------------
__global__ void params_kernel(const float* __restrict__ off_w, const float* __restrict__ off_b,
                              const float* __restrict__ sc_w,  const float* __restrict__ sc_b) {
    int idx = blockIdx.x * blockDim.x + threadIdx.x;
    if (idx >= 2*6*1024) return;
    int wx = idx & 31, wy = (idx >> 5) & 31;
    int h  = (idx >> 10) % 6, b = idx / (6*1024);
    const float* pv = g_pooled + b*192*1024 + wy*32 + wx;
    float ox = off_b[h*2], oy = off_b[h*2+1];
    float sx = sc_b[h*2],  sy = sc_b[h*2+1];
    const float* owx = off_w + (h*2)*192; const float* owy = owx + 192;
    const float* swx = sc_w  + (h*2)*192; const float* swy = swx + 192;
    for (int c = 0; c < 192; c++) {
        float p = pv[c*1024];
        ox += owx[c]*p; oy += owy[c]*p;
        sx += swx[c]*p; sy += swy[c]*p;
    }
    float4 r; r.x = sx; r.y = sy; r.z = ox*(127.5f/32.0f); r.w = oy*(127.5f/32.0f);
    g_params[idx] = r;
}

// ---------------- 2b) rpb table expansion -------------------------------------
__global__ void rpb_kernel(const float* __restrict__ rpb_table) {
    int idx = blockIdx.x * blockDim.x + threadIdx.x;
    if (idx >= 6*4096) return;
    int h = idx / 4096, r = idx & 4095;
    int q = r >> 6, k2 = r & 63;
    int rpi = ((q >> 3) - (k2 >> 3) + 7)*15 + ((q & 7) - (k2 & 7) + 7);
    g_rpb[idx] = rpb_table[rpi*6 + h];
}

// ---------------- weight split: W[M,192] fp32 -> [M,576] bf16 [hi|hi|lo] -------
__global__ void wsplit_kernel(const float* __restrict__ w, int which, int n) {
    int i = blockIdx.x * 256 + threadIdx.x;
    if (i >= n) return;
    __nv_bfloat16* dst = which ? g_wp : g_wq;
    int m = i / 192, k = i - m*192;
    float x = w[i];
    __nv_bfloat16 hi = __float2bfloat16(x);
    float lo = x - __bfloat162float(hi);
    dst[(size_t)m*KTOT + k]           = hi;
    dst[(size_t)m*KTOT + 192 + k]     = hi;
    dst[(size_t)m*KTOT + 384 + k]     = __float2bfloat16(lo);
}

// ---------------- activation transpose+split: [192,HW] -> [HW,576] [hi|lo|hi] --
__global__ void __launch_bounds__(256) convert_kernel(const float* __restrict__ src, int which) {
    __shared__ float tile[192][65];
    __nv_bfloat16* dst = which ? g_lt : g_xt;
    int pix0 = blockIdx.x * 64; int b = blockIdx.y;
    const float* s = src + (size_t)b*192*HW;
    int t = threadIdx.x;
    int cr = t >> 4, p4 = (t & 15) * 4;
    #pragma unroll
    for (int i = 0; i < 12; i++) {
        int c = cr + i*16;
        float4 v = *(const float4*)(s + (size_t)c*HW + pix0 + p4);
        tile[c][p4] = v.x; tile[c][p4+1] = v.y; tile[c][p4+2] = v.z; tile[c][p4+3] = v.w;
    }
    __syncthreads();
    int p = t >> 2, q4 = t & 3;
    __nv_bfloat16* drow = dst + ((size_t)b*HW + pix0 + p)*KTOT;
    #pragma unroll
    for (int v = 0; v < 6; v++) {
        int c0 = q4*48 + v*8;
        __nv_bfloat16 hv[8], lv[8];
        #pragma unroll
        for (int j = 0; j < 8; j++) {
            float x = tile[c0+j][p];
            hv[j] = __float2bfloat16(x);
            lv[j] = __float2bfloat16(x - __bfloat162float(hv[j]));
        }
        *(uint4*)(drow + c0)        = *(uint4*)hv;
        *(uint4*)(drow + 192 + c0)  = *(uint4*)lv;
        *(uint4*)(drow + 384 + c0)  = *(uint4*)hv;
    }
}

// ---------------- HMMA GEMM: D[128pix, 64feat] = A[128,576] * B[64,576]^T ------
// mode 0: A=g_xt, B=g_wq -> qpan/k/v.  mode 1: A=g_lt, B=g_wq(q rows) -> g_q.
// mode 2: A=g_at, B=g_wp -> out (proj bias).
__global__ void __launch_bounds__(256) hgemm(int mode, const float* __restrict__ bias,
                                             float* __restrict__ outp) {
    __shared__ __align__(16) union {
        struct { __nv_bfloat16 a[128][72]; __nv_bfloat16 b[64][72]; } ld;
        float c[64][132];
    } sm;
    int pt = blockIdx.x, ft = blockIdx.y, bz = blockIdx.z;
    const __nv_bfloat16* Abase;
    int b, strm = 0;
    if (mode == 0)      { b = bz; Abase = g_xt + ((size_t)b*HW + pt*128)*KTOT; }
    else if (mode == 1) { b = bz; Abase = g_lt + ((size_t)b*HW + pt*128)*KTOT; }
    else { strm = bz >> 1; b = bz & 1; Abase = g_at + ((size_t)(strm*2+b)*HW + pt*128)*KTOT; }
    const __nv_bfloat16* Bbase = ((mode == 2) ? g_wp : g_wq) + (size_t)ft*64*KTOT;

    int tid = threadIdx.x, wid = tid >> 5;
    int wm = wid & 3, wn = wid >> 2;   // warp tile: 32 pix x 32 feat

    wmma::fragment<wmma::accumulator, 16, 16, 16, float> acc[2][2];
    #pragma unroll
    for (int i = 0; i < 2; i++)
        #pragma unroll
        for (int j = 0; j < 2; j++) wmma::fill_fragment(acc[i][j], 0.0f);

    for (int kk = 0; kk < KTOT; kk += KCH) {
        #pragma unroll
        for (int i = 0; i < 4; i++) {
            int idx = tid + i*256;
            int row = idx >> 3, c8 = (idx & 7)*8;
            *(uint4*)&sm.ld.a[row][c8] = *(const uint4*)(Abase + (size_t)row*KTOT + kk + c8);
        }
        #pragma unroll
        for (int i = 0; i < 2; i++) {
            int idx = tid + i*256;
            int row = idx >> 3, c8 = (idx & 7)*8;
            *(uint4*)&sm.ld.b[row][c8] = *(const uint4*)(Bbase + (size_t)row*KTOT + kk + c8);
        }
        __syncthreads();
        #pragma unroll
        for (int ks = 0; ks < KCH; ks += 16) {
            wmma::fragment<wmma::matrix_a, 16, 16, 16, __nv_bfloat16, wmma::row_major> af[2];
            wmma::fragment<wmma::matrix_b, 16, 16, 16, __nv_bfloat16, wmma::col_major> bf[2];
            wmma::load_matrix_sync(af[0], &sm.ld.a[wm*32][ks], 72);
            wmma::load_matrix_sync(af[1], &sm.ld.a[wm*32 + 16][ks], 72);
            wmma::load_matrix_sync(bf[0], &sm.ld.b[wn*32][ks], 72);
            wmma::load_matrix_sync(bf[1], &sm.ld.b[wn*32 + 16][ks], 72);
            #pragma unroll
            for (int i = 0; i < 2; i++)
                #pragma unroll
                for (int j = 0; j < 2; j++)
                    wmma::mma_sync(acc[i][j], af[i], bf[j], acc[i][j]);
        }
        __syncthreads();
    }
    // epilogue: col-major store to smem (c[feat][pix]), then coalesced global write
    #pragma unroll
    for (int i = 0; i < 2; i++)
        #pragma unroll
        for (int j = 0; j < 2; j++)
            wmma::store_matrix_sync(&sm.c[wn*32 + j*16][wm*32 + i*16], acc[i][j],
                                    132, wmma::mem_col_major);
    __syncthreads();

    int row = tid >> 2;               // feat row 0..63
    int feat = ft*64 + row;
    float bi = bias[feat];
    float* dst;
    if (mode == 0) {
        int which = feat / 192; int cc = feat - which*192;
        float* base = (which == 0) ? g_qpan : ((which == 1) ? g_k : g_v);
        dst = base + ((size_t)(b*192 + cc))*HW;
    } else if (mode == 1) {
        dst = g_q + ((size_t)(b*192 + feat))*HW;
    } else {
        dst = outp + (size_t)strm*((size_t)2*192*HW) + ((size_t)(b*192 + feat))*HW;
    }
    float* dbase = dst + pt*128;
    #pragma unroll
    for (int i = 0; i < 8; i++) {
        int p4 = ((tid & 3) + i*4)*4;
        float4 v = *(float4*)&sm.c[row][p4];
        v.x += bi; v.y += bi; v.z += bi; v.w += bi;
        *(float4*)(dbase + p4) = v;
    }
}

// ---------------- fused grid-sample + window attention (online softmax) --------
__global__ void __launch_bounds__(128) attn_kernel() {
    __shared__ float ksm[64*32];
    __shared__ float vsm[64*32];
    __shared__ float rpbsm[4096];
    __shared__ float gxs[64], gys[64];
    int bx = blockIdx.x;
    int h = bx % 6; int t = bx / 6;
    int wx = t & 31, wy = (t >> 5) & 31, b = t >> 10;
    int tid = threadIdx.x;

    if (tid < 64) {
        int i = tid >> 3, j = tid & 7;
        float4 p = g_params[((b*6 + h)*32 + wy)*32 + wx];
        gxs[tid] = (float)(wx*8 + j) + ((float)j - 3.5f)*p.x + p.z;
        gys[tid] = (float)(wy*8 + i) + ((float)i - 3.5f)*p.y + p.w;
    }
    {
        const float4* src = (const float4*)(g_rpb + h*4096);
        float4* dst4 = (float4*)rpbsm;
        #pragma unroll
        for (int i = 0; i < 8; i++) dst4[tid + i*128] = src[tid + i*128];
    }
    __syncthreads();

    size_t cbase = ((size_t)b*192 + h*32)*HW;
    const float* kb = g_k + cbase;
    const float* vb = g_v + cbase;
    #pragma unroll
    for (int it = 0; it < 16; it++) {
        int idx = tid + it*128;
        int pos = idx & 63, d = idx >> 6;
        float gx = gxs[pos], gy = gys[pos];
        float xf = floorf(gx), yf = floorf(gy);
        int x0 = (int)xf, y0 = (int)yf;
        float fx = gx - xf, fy = gy - yf;
        int off = d*HW;
        float kacc = 0.f, vacc = 0.f;
        bool vx0 = (x0 >= 0) & (x0 < NPIX), vx1 = (x0+1 >= 0) & (x0+1 < NPIX);
        bool vy0 = (y0 >= 0) & (y0 < NPIX), vy1 = (y0+1 >= 0) & (y0+1 < NPIX);
        if (vx0 & vy0) { float w = (1.f-fx)*(1.f-fy); int o = off + y0*256 + x0;       kacc += w*kb[o]; vacc += w*vb[o]; }
        if (vx1 & vy0) { float w = fx*(1.f-fy);       int o = off + y0*256 + x0+1;     kacc += w*kb[o]; vacc += w*vb[o]; }
        if (vx0 & vy1) { float w = (1.f-fx)*fy;       int o = off + (y0+1)*256 + x0;   kacc += w*kb[o]; vacc += w*vb[o]; }
        if (vx1 & vy1) { float w = fx*fy;             int o = off + (y0+1)*256 + x0+1; kacc += w*kb[o]; vacc += w*vb[o]; }
        ksm[pos*32 + d] = kacc;
        vsm[pos*32 + d] = vacc;
    }
    __syncthreads();

    int qi = tid & 63;
    int strm = (tid < 64) ? 0 : 1;
    const float* qb = (strm ? g_qpan : g_q) + cbase;
    int i = qi >> 3, j = qi & 7;
    int pix = (wy*8 + i)*256 + wx*8 + j;
    float qr[32];
    #pragma unroll
    for (int d = 0; d < 32; d++) qr[d] = qb[(size_t)d*HW + pix] * 0.17677669529663687f;

    const float* rpbrow = rpbsm + qi*64;
    float m = -1e30f, l = 0.f;
    float ov[32];
    #pragma unroll
    for (int d = 0; d < 32; d++) ov[d] = 0.f;

    #pragma unroll
    for (int kc = 0; kc < 64; kc += 16) {
        float sc[16];
        float cmax = -1e30f;
        #pragma unroll
        for (int k2 = 0; k2 < 16; k2++) {
            int k = kc + k2;
            float s = 0.f;
            #pragma unroll
            for (int d = 0; d < 32; d++) s += qr[d]*ksm[k*32 + d];
            s += rpbrow[k];
            sc[k2] = s;
            cmax = fmaxf(cmax, s);
        }
        float mnew = fmaxf(m, cmax);
        float corr = __expf(m - mnew);
        l *= corr;
        #pragma unroll
        for (int d = 0; d < 32; d++) ov[d] *= corr;
        #pragma unroll
        for (int k2 = 0; k2 < 16; k2++) {
            float e = __expf(sc[k2] - mnew);
            l += e;
            int k = kc + k2;
            #pragma unroll
            for (int d = 0; d < 32; d++) ov[d] += e*vsm[k*32 + d];
        }
        m = mnew;
    }
    float inv = 1.0f/l;
    #pragma unroll
    for (int d = 0; d < 32; d++) ov[d] *= inv;

    // write split-bf16 [hi|lo|hi] row chunk for proj GEMM
    __nv_bfloat16* drow = g_at + ((size_t)(strm*2 + b)*HW + pix)*KTOT + h*32;
    #pragma unroll
    for (int v = 0; v < 4; v++) {
        __nv_bfloat16 hv[8], lv[8];
        #pragma unroll
        for (int d = 0; d < 8; d++) {
            float x = ov[v*8 + d];
            hv[d] = __float2bfloat16(x);
            lv[d] = __float2bfloat16(x - __bfloat162float(hv[d]));
        }
        *(uint4*)(drow + v*8)        = *(uint4*)hv;
        *(uint4*)(drow + 192 + v*8)  = *(uint4*)lv;
        *(uint4*)(drow + 384 + v*8)  = *(uint4*)hv;
    }
}

// ---------------- launch --------------------------------------------------------
extern "C" void kernel_launch(void* const* d_in, const int* in_sizes, int n_in,
                              void* d_out, int out_size) {
    const float* x      = (const float*)d_in[0];
    const float* lms    = (const float*)d_in[1];
    const float* qkv_w  = (const float*)d_in[2];
    const float* qkv_b  = (const float*)d_in[3];
    const float* off_w  = (const float*)d_in[4];
    const float* off_b  = (const float*)d_in[5];
    const float* sc_w   = (const float*)d_in[6];
    const float* sc_b   = (const float*)d_in[7];
    const float* proj_w = (const float*)d_in[8];
    const float* proj_b = (const float*)d_in[9];
    const float* rpb    = (const float*)d_in[10];
    float* out = (float*)d_out;

    wsplit_kernel<<<(576*192 + 255)/256, 256>>>(qkv_w, 0, 576*192);
    wsplit_kernel<<<(192*192 + 255)/256, 256>>>(proj_w, 1, 192*192);
    convert_kernel<<<dim3(1024, 2), 256>>>(x,   0);
    convert_kernel<<<dim3(1024, 2), 256>>>(lms, 1);
    pool_kernel<<<(2*192*1024 + 255)/256, 256>>>(x);
    params_kernel<<<(2*6*1024 + 255)/256, 256>>>(off_w, off_b, sc_w, sc_b);
    rpb_kernel<<<(6*4096 + 255)/256, 256>>>(rpb);

    hgemm<<<dim3(512, 9, 2), 256>>>(0, qkv_b, nullptr);
    hgemm<<<dim3(512, 3, 2), 256>>>(1, qkv_b, nullptr);
    attn_kernel<<<2*32*32*6, 128>>>();
    hgemm<<<dim3(512, 3, 4), 256>>>(2, proj_b, out);
}